// round 8
// baseline (speedup 1.0000x reference)
#include <cuda_runtime.h>
#include <cuda_bf16.h>
#include <math_constants.h>

// Problem constants (fixed: B=4, N=M=8192, C=3, k=16)
#define BB 4
#define NN 8192
#define MM 8192
#define KK 16
#define SPLIT 4
#define CHUNK (MM / SPLIT)          // 2048 candidates per thread
#define SUB 512                     // sub-tile resident in smem
#define NSUB (CHUNK / SUB)          // 4
#define NW (SUB / 32)               // 16 mask words per sub-tile
#define NG (NW / 4)                 // 4 uint4 groups per sub-tile
#define BLOCK 128
#define NQ (BB * NN)                // 32768 queries
#define NT (NQ * SPLIT)             // 131072 chunk-threads
#define SAMPLE_M 128
#define SAMPLE_R 6                  // threshold = 6th-closest of sample
#define SLACK 1e-3f

// Static scratch
__device__ float4 g_p2[BB * MM];             // packed candidates (x,y,z,-0.5*|p|^2)
__device__ uint4  g_mask[NSUB * NG * NT];    // keep-masks, [group][thread], 33.5 MB
__device__ float  g_thr[NT];                 // per-chunk-thread Tcert
__device__ float  g_pd[NT * KK];             // per-chunk partial dists (sorted)
__device__ int    g_pi[NT * KK];             // per-chunk partial ids

// ---------------------------------------------------------------------------
// Prep: pack xyz2 -> float4. Norm uses reference rounding ((x*x+y*y)+z*z);
// stored w = -0.5*n is EXACT (power-of-two multiply).
// ---------------------------------------------------------------------------
__global__ void knn_prep(const float* __restrict__ xyz2) {
    int t = blockIdx.x * blockDim.x + threadIdx.x;
    if (t < BB * MM) {
        float x = xyz2[3 * t + 0];
        float y = xyz2[3 * t + 1];
        float z = xyz2[3 * t + 2];
        float n = __fadd_rn(__fadd_rn(__fmul_rn(x, x), __fmul_rn(y, y)),
                            __fmul_rn(z, z));
        g_p2[t] = make_float4(x, y, z, __fmul_rn(-0.5f, n));
    }
}

// Exact reference-rounded d2 (identical arithmetic to the validated kernels).
__device__ __forceinline__ float dist2x(float4 p, float x, float y, float z, float n1) {
    float dot = __fmaf_rn(z, p.z, __fmaf_rn(y, p.y, __fmul_rn(x, p.x)));
    float n2  = __fmul_rn(-2.0f, p.w);
    return __fadd_rn(__fadd_rn(__fmul_rn(-2.0f, dot), n1), n2);
}

// Filter metric: val = dot - n2/2 (3 FMAs). Larger val == closer.
__device__ __forceinline__ float fval(float4 p, float x, float y, float z) {
    return __fmaf_rn(x, p.x, __fmaf_rn(y, p.y, __fmaf_rn(z, p.z, p.w)));
}

#define INSERT16(d2v, civ)                                              \
    do {                                                                \
        _Pragma("unroll")                                               \
        for (int jj = KK - 1; jj > 0; --jj) {                           \
            bool sh = (d2v) < dk[jj - 1];                               \
            bool he = (!sh) && ((d2v) < dk[jj]);                        \
            float nd = sh ? dk[jj - 1] : (he ? (d2v) : dk[jj]);         \
            int   ni = sh ? idv[jj - 1] : (he ? (civ) : idv[jj]);       \
            dk[jj] = nd; idv[jj] = ni;                                  \
        }                                                               \
        if ((d2v) < dk[0]) { dk[0] = (d2v); idv[0] = (civ); }           \
    } while (0)

// ---------------------------------------------------------------------------
// Kernel A: mask build only. No top-k state -> low regs, high occupancy.
// ---------------------------------------------------------------------------
__global__ void __launch_bounds__(BLOCK, 10) knn_mask(const float* __restrict__ xyz1) {
    __shared__ float4 tile[SUB];                  // 8 KB

    const int tid  = threadIdx.x;
    const int gtid = blockIdx.x * BLOCK + tid;
    const int s = blockIdx.x & (SPLIT - 1);
    const int q = (blockIdx.x >> 2) * BLOCK + tid;
    const int b = q >> 13;
    const float4* __restrict__ src = g_p2 + b * MM + s * CHUNK;

    const float x = xyz1[3 * q + 0];
    const float y = xyz1[3 * q + 1];
    const float z = xyz1[3 * q + 2];
    const float n1 = __fadd_rn(__fadd_rn(__fmul_rn(x, x), __fmul_rn(y, y)),
                               __fmul_rn(z, z));

    float hqd = 0.0f;

    for (int st = 0; st < NSUB; ++st) {
        __syncthreads();
#pragma unroll
        for (int i = tid; i < SUB; i += BLOCK)
            tile[i] = src[st * SUB + i];
        __syncthreads();

        if (st == 0) {
            // Threshold: branchless LARGEST-6 val chain over first 128 cands.
            float sl[SAMPLE_R];
#pragma unroll
            for (int i = 0; i < SAMPLE_R; ++i) sl[i] = -CUDART_INF_F;
#pragma unroll 4
            for (int j = 0; j < SAMPLE_M; ++j) {
                float v = fval(tile[j], x, y, z);
#pragma unroll
                for (int jj = SAMPLE_R - 1; jj > 0; --jj)
                    sl[jj] = fmaxf(fminf(v, sl[jj - 1]), sl[jj]);
                sl[0] = fmaxf(sl[0], v);
            }
            float hq = sl[SAMPLE_R - 1];
            hqd = hq - SLACK;
            g_thr[gtid] = __fadd_rn(__fmaf_rn(-2.0f, hq, n1), SLACK);
        }

        for (int g = 0; g < NG; ++g) {
            unsigned r[4];
#pragma unroll
            for (int w = 0; w < 4; ++w) {
                const int j0 = (g * 4 + w) * 32;
                // 4 independent 8-bit accumulators -> dependency chain / 4
                unsigned m0 = 0, m1 = 0, m2 = 0, m3 = 0;
#pragma unroll
                for (int i = 0; i < 8; ++i) {
                    float v0 = fval(tile[j0 + 4 * i + 0], x, y, z);
                    float v1 = fval(tile[j0 + 4 * i + 1], x, y, z);
                    float v2 = fval(tile[j0 + 4 * i + 2], x, y, z);
                    float v3 = fval(tile[j0 + 4 * i + 3], x, y, z);
                    if (v0 >= hqd) m0 |= (1u << (4 * i + 0));
                    if (v1 >= hqd) m1 |= (1u << (4 * i + 1));
                    if (v2 >= hqd) m2 |= (1u << (4 * i + 2));
                    if (v3 >= hqd) m3 |= (1u << (4 * i + 3));
                }
                r[w] = (m0 | m1) | (m2 | m3);
            }
            g_mask[(st * NG + g) * NT + gtid] = make_uint4(r[0], r[1], r[2], r[3]);
        }
    }
}

// ---------------------------------------------------------------------------
// Kernel B: refine. Reads masks, exact d2 on survivors, certify, sort, write.
// ---------------------------------------------------------------------------
__global__ void __launch_bounds__(BLOCK, 7) knn_refine(const float* __restrict__ xyz1) {
    __shared__ float4 tile[SUB];                  // 8 KB

    const int tid  = threadIdx.x;
    const int gtid = blockIdx.x * BLOCK + tid;
    const int s = blockIdx.x & (SPLIT - 1);
    const int q = (blockIdx.x >> 2) * BLOCK + tid;
    const int b = q >> 13;
    const int cbase = s * CHUNK;
    const float4* __restrict__ src = g_p2 + b * MM + cbase;

    const float x = xyz1[3 * q + 0];
    const float y = xyz1[3 * q + 1];
    const float z = xyz1[3 * q + 2];
    const float n1 = __fadd_rn(__fadd_rn(__fmul_rn(x, x), __fmul_rn(y, y)),
                               __fmul_rn(z, z));
    const float Tcert = g_thr[gtid];

    float dk[KK];
    int   idv[KK];
#pragma unroll
    for (int i = 0; i < KK; ++i) { dk[i] = CUDART_INF_F; idv[i] = 0; }
    int c16 = 0;

    for (int st = 0; st < NSUB; ++st) {
        __syncthreads();
#pragma unroll
        for (int i = tid; i < SUB; i += BLOCK)
            tile[i] = src[st * SUB + i];
        __syncthreads();

        const int sbase = cbase + st * SUB;
        for (int g = 0; g < NG; ++g) {
            uint4 mw = g_mask[(st * NG + g) * NT + gtid];
            unsigned ms[4] = {mw.x, mw.y, mw.z, mw.w};
#pragma unroll
            for (int w = 0; w < 4; ++w) {
                unsigned m = ms[w];
                const int j0 = (g * 4 + w) * 32;
                while (m) {
                    int bb = __ffs(m) - 1;
                    m &= m - 1;
                    int j = j0 + bb;
                    float d2 = dist2x(tile[j], x, y, z, n1);
                    c16 += (d2 <= Tcert);
                    if (d2 < dk[KK - 1]) {
                        int ci = sbase + j;
                        INSERT16(d2, ci);
                    }
                }
            }
        }
    }

    if (c16 < KK) {
        // Exact fallback (threshold too tight — astronomically rare)
#pragma unroll
        for (int i = 0; i < KK; ++i) { dk[i] = CUDART_INF_F; idv[i] = 0; }
        for (int j = 0; j < CHUNK; ++j) {
            float4 p = src[j];
            float d2 = dist2x(p, x, y, z, n1);
            if (d2 < dk[KK - 1]) {
                int ci = cbase + j;
                INSERT16(d2, ci);
            }
        }
    }

    // sqrt, stable (dist, idx) sort, write partial results
    float dist[KK];
#pragma unroll
    for (int i = 0; i < KK; ++i) dist[i] = __fsqrt_rn(dk[i]);

#pragma unroll
    for (int ph = 0; ph < KK; ++ph) {
#pragma unroll
        for (int i = 0; i < KK - 1; ++i) {
            if ((i & 1) == (ph & 1)) {
                bool sw = (dist[i] > dist[i + 1]) ||
                          (dist[i] == dist[i + 1] && idv[i] > idv[i + 1]);
                float td = sw ? dist[i + 1] : dist[i];
                float tD = sw ? dist[i]     : dist[i + 1];
                int   ti = sw ? idv[i + 1]  : idv[i];
                int   tI = sw ? idv[i]      : idv[i + 1];
                dist[i] = td; dist[i + 1] = tD;
                idv[i]  = ti; idv[i + 1]  = tI;
            }
        }
    }

    const int r = (q * SPLIT + s) * KK;
#pragma unroll
    for (int i = 0; i < KK; ++i) {
        g_pd[r + i] = dist[i];
        g_pi[r + i] = idv[i];
    }
}

// ---------------------------------------------------------------------------
// Merge: per query, 4-way merge of sorted (dist, idx) partial lists -> top-16.
// ---------------------------------------------------------------------------
__global__ void knn_merge(float* __restrict__ out, int write_both) {
    int q = blockIdx.x * blockDim.x + threadIdx.x;
    if (q >= NQ) return;

    const int r0 = (q * SPLIT + 0) * KK;
    const int r1 = (q * SPLIT + 1) * KK;
    const int r2 = (q * SPLIT + 2) * KK;
    const int r3 = (q * SPLIT + 3) * KK;

    int h0 = 0, h1 = 0, h2 = 0, h3 = 0;
    float d0 = g_pd[r0], d1 = g_pd[r1], d2 = g_pd[r2], d3 = g_pd[r3];
    int   i0 = g_pi[r0], i1 = g_pi[r1], i2 = g_pi[r2], i3 = g_pi[r3];

    const long base = (long)q * KK;
    const long off = (long)NQ * KK;

#pragma unroll
    for (int k = 0; k < KK; ++k) {
        bool l01 = (d0 < d1) || (d0 == d1 && i0 < i1);
        float dA = l01 ? d0 : d1; int iA = l01 ? i0 : i1;
        bool l23 = (d2 < d3) || (d2 == d3 && i2 < i3);
        float dB = l23 ? d2 : d3; int iB = l23 ? i2 : i3;
        bool lAB = (dA < dB) || (dA == dB && iA < iB);
        float dw = lAB ? dA : dB; int iw = lAB ? iA : iB;

        out[base + k] = dw;
        if (write_both) out[off + base + k] = (float)iw;

        int pick = lAB ? (l01 ? 0 : 1) : (l23 ? 2 : 3);
        if (pick == 0) {
            ++h0; bool v = h0 < KK;
            d0 = v ? g_pd[r0 + h0] : CUDART_INF_F;
            i0 = v ? g_pi[r0 + h0] : 0x7fffffff;
        } else if (pick == 1) {
            ++h1; bool v = h1 < KK;
            d1 = v ? g_pd[r1 + h1] : CUDART_INF_F;
            i1 = v ? g_pi[r1 + h1] : 0x7fffffff;
        } else if (pick == 2) {
            ++h2; bool v = h2 < KK;
            d2 = v ? g_pd[r2 + h2] : CUDART_INF_F;
            i2 = v ? g_pi[r2 + h2] : 0x7fffffff;
        } else {
            ++h3; bool v = h3 < KK;
            d3 = v ? g_pd[r3 + h3] : CUDART_INF_F;
            i3 = v ? g_pi[r3 + h3] : 0x7fffffff;
        }
    }
}

extern "C" void kernel_launch(void* const* d_in, const int* in_sizes, int n_in,
                              void* d_out, int out_size) {
    const float* xyz1 = (const float*)d_in[0];
    const float* xyz2 = (const float*)d_in[1];
    float* out = (float*)d_out;

    int write_both = (out_size >= 2 * NQ * KK) ? 1 : 0;

    knn_prep<<<(BB * MM + 255) / 256, 256>>>(xyz2);
    knn_mask<<<NT / BLOCK, BLOCK>>>(xyz1);
    knn_refine<<<NT / BLOCK, BLOCK>>>(xyz1);
    knn_merge<<<(NQ + 255) / 256, 256>>>(out, write_both);
}